// round 5
// baseline (speedup 1.0000x reference)
#include <cuda_runtime.h>
#include <math_constants.h>

#define BB 64
#define NN 512
#define NTHREADS 512

__global__ void init_out_kernel(float* out) {
    out[0] = 0.0f;
    out[1] = 0.0f;
}

__global__ __launch_bounds__(NTHREADS) void chamfer_split_pid_kernel(
    const float4* __restrict__ target,   // [B*N] float4 (D=4)
    const float4* __restrict__ reco,     // [B*N] float4
    const int* __restrict__ in_pid,      // [B*N]
    const int* __restrict__ out_pid,     // [B*N]
    float* __restrict__ out)             // [2]: loss_nonzero, loss_zero
{
    __shared__ float4 gt[NN];            // target points grouped by in_pid
    __shared__ float4 gr[NN];            // reco points grouped by out_pid
    __shared__ unsigned char gct[NN];    // class of grouped target entry
    __shared__ unsigned char gcr[NN];    // class of grouped reco entry
    __shared__ int cx[5], cy[5];         // class counts
    __shared__ int ox[6], oy[6];         // group offsets
    __shared__ int curx[5], cury[5];     // scatter cursors
    __shared__ float sx[5], sy[5];       // sum of norms per class (full batch)
    __shared__ float sacc[5];            // this CTA's direction partial sums

    const int b = blockIdx.x >> 1;       // batch index
    const int half = blockIdx.x & 1;     // 0: x->y direction, 1: y->x direction
    const int tid = threadIdx.x;
    const int base = b * NN;

    if (tid < 5) {
        cx[tid] = 0; cy[tid] = 0;
        sx[tid] = 0.0f; sy[tid] = 0.0f;
        sacc[tid] = 0.0f;
    }
    __syncthreads();

    // ---- Pass 1: class counts (one element per thread) ----
    {
        atomicAdd(&cx[in_pid[base + tid]], 1);
        atomicAdd(&cy[out_pid[base + tid]], 1);
    }
    __syncthreads();

    if (tid == 0) {
        int a = 0, c = 0;
        #pragma unroll
        for (int p = 0; p < 5; p++) {
            ox[p] = a; a += cx[p];
            oy[p] = c; c += cy[p];
            curx[p] = ox[p];
            cury[p] = oy[p];
        }
        ox[5] = a; oy[5] = c;
    }
    __syncthreads();

    // ---- Pass 2: scatter into pid-contiguous groups + norm sums ----
    // Scatter order within a group is arbitrary (atomicAdd), which is safe:
    // this CTA iterates its OWN permutation for the full direction it owns,
    // and group membership is order-invariant for the min-search.
    {
        int p = in_pid[base + tid];
        float4 t = target[base + tid];
        int pos = atomicAdd(&curx[p], 1);
        gt[pos] = t;
        gct[pos] = (unsigned char)p;
        float nt = sqrtf(t.x * t.x + t.y * t.y + t.z * t.z + t.w * t.w);
        atomicAdd(&sx[p], nt);

        int q = out_pid[base + tid];
        float4 r = reco[base + tid];
        int qpos = atomicAdd(&cury[q], 1);
        gr[qpos] = r;
        gcr[qpos] = (unsigned char)q;
        float nr = sqrtf(r.x * r.x + r.y * r.y + r.z * r.z + r.w * r.w);
        atomicAdd(&sy[q], nr);
    }
    __syncthreads();

    // One grouped entry per thread; entries are pid-grouped so consecutive
    // lanes share a class -> inner-loop LDS reads are warp-uniform broadcasts.
    // 4 independent min accumulators break the FMNMX dependency chain.
    if (half == 0) {
        // ---- Direction x->y: target entry tid (class p>=1) vs reco group p ----
        int p = gct[tid];
        int jb = oy[p], je = oy[p + 1];
        if (p != 0 && jb != je) {          // cy[p]==0: only_x branch handles it
            float4 t = gt[tid];
            float m0 = CUDART_INF_F, m1 = CUDART_INF_F;
            float m2 = CUDART_INF_F, m3 = CUDART_INF_F;
            int j = jb;
            for (; j + 3 < je; j += 4) {
                float4 r0 = gr[j + 0];
                float4 r1 = gr[j + 1];
                float4 r2 = gr[j + 2];
                float4 r3 = gr[j + 3];
                float dx, dy, dz, dw, d2;
                dx = t.x - r0.x; dy = t.y - r0.y; dz = t.z - r0.z; dw = t.w - r0.w;
                d2 = dx * dx + dy * dy + dz * dz + dw * dw; m0 = fminf(m0, d2);
                dx = t.x - r1.x; dy = t.y - r1.y; dz = t.z - r1.z; dw = t.w - r1.w;
                d2 = dx * dx + dy * dy + dz * dz + dw * dw; m1 = fminf(m1, d2);
                dx = t.x - r2.x; dy = t.y - r2.y; dz = t.z - r2.z; dw = t.w - r2.w;
                d2 = dx * dx + dy * dy + dz * dz + dw * dw; m2 = fminf(m2, d2);
                dx = t.x - r3.x; dy = t.y - r3.y; dz = t.z - r3.z; dw = t.w - r3.w;
                d2 = dx * dx + dy * dy + dz * dz + dw * dw; m3 = fminf(m3, d2);
            }
            for (; j < je; j++) {
                float4 r = gr[j];
                float dx = t.x - r.x, dy = t.y - r.y, dz = t.z - r.z, dw = t.w - r.w;
                m0 = fminf(m0, dx * dx + dy * dy + dz * dz + dw * dw);
            }
            float m = fminf(fminf(m0, m1), fminf(m2, m3));
            atomicAdd(&sacc[p], sqrtf(m));   // sacc[p] == sum_xy for class p
        }
    } else {
        // ---- Direction y->x: reco entry tid (class p>=1) vs target group p ----
        int p = gcr[tid];
        int jb = ox[p], je = ox[p + 1];
        if (p != 0 && jb != je) {          // cx[p]==0: only_y branch handles it
            float4 t = gr[tid];
            float m0 = CUDART_INF_F, m1 = CUDART_INF_F;
            float m2 = CUDART_INF_F, m3 = CUDART_INF_F;
            int j = jb;
            for (; j + 3 < je; j += 4) {
                float4 r0 = gt[j + 0];
                float4 r1 = gt[j + 1];
                float4 r2 = gt[j + 2];
                float4 r3 = gt[j + 3];
                float dx, dy, dz, dw, d2;
                dx = t.x - r0.x; dy = t.y - r0.y; dz = t.z - r0.z; dw = t.w - r0.w;
                d2 = dx * dx + dy * dy + dz * dz + dw * dw; m0 = fminf(m0, d2);
                dx = t.x - r1.x; dy = t.y - r1.y; dz = t.z - r1.z; dw = t.w - r1.w;
                d2 = dx * dx + dy * dy + dz * dz + dw * dw; m1 = fminf(m1, d2);
                dx = t.x - r2.x; dy = t.y - r2.y; dz = t.z - r2.z; dw = t.w - r2.w;
                d2 = dx * dx + dy * dy + dz * dz + dw * dw; m2 = fminf(m2, d2);
                dx = t.x - r3.x; dy = t.y - r3.y; dz = t.z - r3.z; dw = t.w - r3.w;
                d2 = dx * dx + dy * dy + dz * dz + dw * dw; m3 = fminf(m3, d2);
            }
            for (; j < je; j++) {
                float4 r = gt[j];
                float dx = t.x - r.x, dy = t.y - r.y, dz = t.z - r.z, dw = t.w - r.w;
                m0 = fminf(m0, dx * dx + dy * dy + dz * dz + dw * dw);
            }
            float m = fminf(fminf(m0, m1), fminf(m2, m3));
            atomicAdd(&sacc[p], sqrtf(m));   // sacc[p] == sum_yx for class p
        }
    }
    __syncthreads();

    // ---- Per-batch combine + global accumulate ----
    // Both CTAs see identical counts and sx/sy, so branch conditions agree.
    // half==0 contributes: 0.5*sum_xy/cy (both-branch), only_x (cy==0), loss_zero.
    // half==1 contributes: 0.5*sum_yx/cx (both-branch), only_y (cx==0 && cy>0).
    if (tid == 0) {
        const float invB = 1.0f / (float)BB;
        float lnz = 0.0f;
        #pragma unroll
        for (int p = 1; p < 5; p++) {
            if (cy[p] == 0) {
                if (half == 0) lnz += sx[p] / (float)max(1, cx[p]);
            } else if (cx[p] == 0) {
                if (half == 1) lnz += sy[p] / (float)max(1, cy[p]);
            } else {
                lnz += (half == 0) ? 0.5f * (sacc[p] / (float)cy[p])
                                   : 0.5f * (sacc[p] / (float)cx[p]);
            }
        }
        atomicAdd(&out[0], lnz * invB);
        if (half == 0) {
            float lz = sy[0] / (float)max(1, cy[0]);
            atomicAdd(&out[1], lz * invB);
        }
    }
}

extern "C" void kernel_launch(void* const* d_in, const int* in_sizes, int n_in,
                              void* d_out, int out_size) {
    const float4* target = (const float4*)d_in[0];
    const float4* reco   = (const float4*)d_in[1];
    const int* in_pid    = (const int*)d_in[2];
    const int* out_pid   = (const int*)d_in[3];
    float* out = (float*)d_out;

    init_out_kernel<<<1, 32>>>(out);
    chamfer_split_pid_kernel<<<BB * 2, NTHREADS>>>(target, reco, in_pid, out_pid, out);
}

// round 12
// speedup vs baseline: 1.4009x; 1.4009x over previous
#include <cuda_runtime.h>
#include <math_constants.h>

#define BB 64
#define NN 512
#define NT 256          // threads per CTA
#define NW 8            // warps per CTA
#define NVW 16          // virtual warps = 2 rounds x 8 warps

__global__ void init_out_kernel(float* out) {
    out[0] = 0.0f;
    out[1] = 0.0f;
}

__global__ __launch_bounds__(NT) void chamfer_split_pid_kernel(
    const float4* __restrict__ target,   // [B*N] float4 (D=4)
    const float4* __restrict__ reco,     // [B*N] float4
    const int* __restrict__ in_pid,      // [B*N]
    const int* __restrict__ out_pid,     // [B*N]
    float* __restrict__ out)             // [2]: loss_nonzero, loss_zero
{
    __shared__ float4 gt[NN], gr[NN];        // points grouped by pid (deterministic)
    __shared__ float  ht[NN], hr[NN];        // 0.5*|point|^2 at grouped position
    __shared__ unsigned char gct[NN], gcr[NN];
    __shared__ int wpx[NVW][5], wpy[NVW][5]; // per-virtual-warp class counts -> exclusive prefix
    __shared__ int cx[5], cy[5];
    __shared__ int ox[6], oy[6];
    __shared__ float sx[5], sy[5];           // per-class norm sums (full batch)
    __shared__ float sacc[5];                // this CTA's partial chamfer sums

    const int b   = blockIdx.x >> 2;         // batch
    const int dir = (blockIdx.x >> 1) & 1;   // 0: x->y, 1: y->x
    const int sub = blockIdx.x & 1;          // which half of the grouped range
    const int tid = threadIdx.x;
    const int wid = tid >> 5;
    const int lane = tid & 31;
    const unsigned ltmask = (1u << lane) - 1u;
    const int base = b * NN;

    if (tid < 5) { sx[tid] = 0.0f; sy[tid] = 0.0f; sacc[tid] = 0.0f; }

    // ---- Deterministic grouping: ballot ranks + cross-warp prefix scan ----
    // Every CTA of a batch computes the IDENTICAL permutation, so splitting
    // the grouped range across CTAs is safe.
    int pA[2], pB[2], rkA[2], rkB[2];
    float4 tA[2], rB[2];
    #pragma unroll
    for (int rnd = 0; rnd < 2; rnd++) {
        int e  = tid + rnd * NT;
        int vw = wid + rnd * NW;
        pA[rnd] = in_pid[base + e];
        pB[rnd] = out_pid[base + e];
        tA[rnd] = target[base + e];
        rB[rnd] = reco[base + e];
        rkA[rnd] = 0; rkB[rnd] = 0;
        #pragma unroll
        for (int c = 0; c < 5; c++) {
            unsigned mA = __ballot_sync(0xffffffffu, pA[rnd] == c);
            unsigned mB = __ballot_sync(0xffffffffu, pB[rnd] == c);
            if (pA[rnd] == c) rkA[rnd] = __popc(mA & ltmask);
            if (pB[rnd] == c) rkB[rnd] = __popc(mB & ltmask);
            if (lane == 0) { wpx[vw][c] = __popc(mA); wpy[vw][c] = __popc(mB); }
        }
    }
    __syncthreads();

    if (tid < 5) {   // 5 threads, each scans its class over 16 virtual warps
        int s = 0;
        #pragma unroll
        for (int v = 0; v < NVW; v++) { int c0 = wpx[v][tid]; wpx[v][tid] = s; s += c0; }
        cx[tid] = s;
        s = 0;
        #pragma unroll
        for (int v = 0; v < NVW; v++) { int c0 = wpy[v][tid]; wpy[v][tid] = s; s += c0; }
        cy[tid] = s;
    }
    __syncthreads();
    if (tid == 0) {
        int a = 0, c = 0;
        #pragma unroll
        for (int p = 0; p < 5; p++) { ox[p] = a; a += cx[p]; oy[p] = c; c += cy[p]; }
        ox[5] = a; oy[5] = c;
    }
    __syncthreads();

    // ---- Scatter to grouped arrays + norm sums + h = 0.5*|v|^2 ----
    #pragma unroll
    for (int rnd = 0; rnd < 2; rnd++) {
        int vw = wid + rnd * NW;
        {
            int p = pA[rnd]; float4 t = tA[rnd];
            int pos = ox[p] + wpx[vw][p] + rkA[rnd];
            gt[pos] = t; gct[pos] = (unsigned char)p;
            float sq = t.x * t.x + t.y * t.y + t.z * t.z + t.w * t.w;
            ht[pos] = 0.5f * sq;
            atomicAdd(&sx[p], sqrtf(sq));
        }
        {
            int q = pB[rnd]; float4 r = rB[rnd];
            int pos = oy[q] + wpy[vw][q] + rkB[rnd];
            gr[pos] = r; gcr[pos] = (unsigned char)q;
            float sq = r.x * r.x + r.y * r.y + r.z * r.z + r.w * r.w;
            hr[pos] = 0.5f * sq;
            atomicAdd(&sy[q], sqrtf(sq));
        }
    }
    __syncthreads();

    // ---- Min phase: min_j d^2 = |t|^2 + 2*min_j( h[j] - t.r_j ) ----
    // This CTA: direction `dir`, half `sub` of the active grouped range.
    // Entries are pid-grouped: consecutive lanes share a class -> warp-uniform
    // LDS broadcasts in the inner loop.
    if (dir == 0) {
        int lo0 = ox[1];                      // skip class-0 target entries
        int mid = lo0 + ((NN - lo0) >> 1);
        int lo = sub ? mid : lo0;
        int hi = sub ? NN  : mid;
        int k = lo + tid;
        if (k < hi) {
            int p = gct[k];
            int jb = oy[p], je = oy[p + 1];
            if (jb != je) {                   // cy[p]==0 handled by only_x branch
                float4 t = gt[k];
                float nx = -t.x, ny = -t.y, nz = -t.z, nw = -t.w;
                float m0 = CUDART_INF_F, m1 = CUDART_INF_F;
                int j = jb;
                #pragma unroll 4
                for (; j + 1 < je; j += 2) {
                    float4 r0 = gr[j], r1 = gr[j + 1];
                    float a0 = fmaf(nx, r0.x, fmaf(ny, r0.y, fmaf(nz, r0.z, fmaf(nw, r0.w, hr[j]))));
                    float a1 = fmaf(nx, r1.x, fmaf(ny, r1.y, fmaf(nz, r1.z, fmaf(nw, r1.w, hr[j + 1]))));
                    m0 = fminf(m0, a0);
                    m1 = fminf(m1, a1);
                }
                if (j < je) {
                    float4 r0 = gr[j];
                    m0 = fminf(m0, fmaf(nx, r0.x, fmaf(ny, r0.y, fmaf(nz, r0.z, fmaf(nw, r0.w, hr[j])))));
                }
                float m = fminf(m0, m1);
                float d = sqrtf(fmaxf(2.0f * ht[k] + 2.0f * m, 0.0f));
                atomicAdd(&sacc[p], d);       // partial sum_xy for class p
            }
        }
    } else {
        int lo0 = oy[1];                      // skip class-0 reco entries
        int mid = lo0 + ((NN - lo0) >> 1);
        int lo = sub ? mid : lo0;
        int hi = sub ? NN  : mid;
        int k = lo + tid;
        if (k < hi) {
            int p = gcr[k];
            int jb = ox[p], je = ox[p + 1];
            if (jb != je) {                   // cx[p]==0 handled by only_y branch
                float4 t = gr[k];
                float nx = -t.x, ny = -t.y, nz = -t.z, nw = -t.w;
                float m0 = CUDART_INF_F, m1 = CUDART_INF_F;
                int j = jb;
                #pragma unroll 4
                for (; j + 1 < je; j += 2) {
                    float4 r0 = gt[j], r1 = gt[j + 1];
                    float a0 = fmaf(nx, r0.x, fmaf(ny, r0.y, fmaf(nz, r0.z, fmaf(nw, r0.w, ht[j]))));
                    float a1 = fmaf(nx, r1.x, fmaf(ny, r1.y, fmaf(nz, r1.z, fmaf(nw, r1.w, ht[j + 1]))));
                    m0 = fminf(m0, a0);
                    m1 = fminf(m1, a1);
                }
                if (j < je) {
                    float4 r0 = gt[j];
                    m0 = fminf(m0, fmaf(nx, r0.x, fmaf(ny, r0.y, fmaf(nz, r0.z, fmaf(nw, r0.w, ht[j])))));
                }
                float m = fminf(m0, m1);
                float d = sqrtf(fmaxf(2.0f * hr[k] + 2.0f * m, 0.0f));
                atomicAdd(&sacc[p], d);       // partial sum_yx for class p
            }
        }
    }
    __syncthreads();

    // ---- Combine ----
    // All 4 CTAs of a batch see identical counts/sx/sy (deterministic scan),
    // so branch decisions agree. Linear chamfer terms: every CTA adds its
    // partial. Branch-only terms contributed once each:
    //   only_x + loss_zero by (dir=0,sub=0); only_y by (dir=1,sub=0).
    if (tid == 0) {
        const float invB = 1.0f / (float)BB;
        float lnz = 0.0f;
        #pragma unroll
        for (int p = 1; p < 5; p++) {
            if (cy[p] == 0) {
                if (dir == 0 && sub == 0) lnz += sx[p] / (float)max(1, cx[p]);
            } else if (cx[p] == 0) {
                if (dir == 1 && sub == 0) lnz += sy[p] / (float)max(1, cy[p]);
            } else {
                lnz += 0.5f * sacc[p] / (dir == 0 ? (float)cy[p] : (float)cx[p]);
            }
        }
        atomicAdd(&out[0], lnz * invB);
        if (dir == 0 && sub == 0) {
            float lz = sy[0] / (float)max(1, cy[0]);
            atomicAdd(&out[1], lz * invB);
        }
    }
}

extern "C" void kernel_launch(void* const* d_in, const int* in_sizes, int n_in,
                              void* d_out, int out_size) {
    const float4* target = (const float4*)d_in[0];
    const float4* reco   = (const float4*)d_in[1];
    const int* in_pid    = (const int*)d_in[2];
    const int* out_pid   = (const int*)d_in[3];
    float* out = (float*)d_out;

    init_out_kernel<<<1, 32>>>(out);
    chamfer_split_pid_kernel<<<BB * 4, NT>>>(target, reco, in_pid, out_pid, out);
}